// round 1
// baseline (speedup 1.0000x reference)
#include <cuda_runtime.h>
#include <math.h>

// Global-likelihood accumulator (device global: no allocation allowed).
__device__ double g_ll;

__global__ void zero_ll_kernel() { g_ll = 0.0; }

__global__ void finalize_ll_kernel(float* __restrict__ out_ll) {
    *out_ll = (float)g_ll;
}

#define T_STEPS 64
#define NCHUNK  16   // T/4 float4 chunks

__global__ __launch_bounds__(256, 4)
void hmm_filter_kernel(
    const float* __restrict__ G,   // (N,1)
    const float* __restrict__ S,   // (N,T)
    const float* __restrict__ C,   // (N,T)
    const float* __restrict__ Y,   // (N,T)
    const float* __restrict__ L,   // (N,3)
    const float* __restrict__ p_psi,
    const float* __restrict__ p_gS,
    const float* __restrict__ p_gC,
    const float* __restrict__ p_gG,
    const float* __restrict__ p_gGS,
    const float* __restrict__ p_gGC,
    const float* __restrict__ p_gLw,   // (1,3)
    const float* __restrict__ p_lsz,
    const float* __restrict__ p_b0,
    const float* __restrict__ p_bZ,
    const float* __restrict__ p_bS,
    const float* __restrict__ p_bG,
    const float* __restrict__ p_bGS,
    const float* __restrict__ p_bLw,   // (1,3)
    float* __restrict__ Zf,            // (N,T)
    float* __restrict__ Zv,            // (N,T)
    int N)
{
    // ---- scalar params (uniform; L1/const-cached broadcasts) ----
    const float psi  = __ldg(p_psi);
    const float gS   = __ldg(p_gS);
    const float gC   = __ldg(p_gC);
    const float gG   = __ldg(p_gG);
    const float gGS  = __ldg(p_gGS);
    const float gGC  = __ldg(p_gGC);
    const float lsz  = __ldg(p_lsz);
    const float b0   = __ldg(p_b0);
    const float bZ   = __ldg(p_bZ);
    const float bS   = __ldg(p_bS);
    const float bG   = __ldg(p_bG);
    const float bGS  = __ldg(p_bGS);
    const float gw0  = __ldg(p_gLw + 0), gw1 = __ldg(p_gLw + 1), gw2 = __ldg(p_gLw + 2);
    const float bw0  = __ldg(p_bLw + 0), bw1 = __ldg(p_bLw + 1), bw2 = __ldg(p_bLw + 2);

    const float sz     = expf(lsz);
    const float sigma2 = sz * sz;
    const float psi2   = psi * psi;
    const float bZ2    = bZ * bZ;

    const int n = blockIdx.x * blockDim.x + threadIdx.x;

    float ll = 0.0f;

    if (n < N) {
        const float Gn = __ldg(G + n);
        const float l0 = __ldg(L + 3 * (size_t)n + 0);
        const float l1 = __ldg(L + 3 * (size_t)n + 1);
        const float l2 = __ldg(L + 3 * (size_t)n + 2);

        // Per-row fused constants
        const float gL  = fmaf(gw0, l0, fmaf(gw1, l1, gw2 * l2));
        const float bL  = fmaf(bw0, l0, fmaf(bw1, l1, bw2 * l2));
        const float tc0 = fmaf(gG, Gn, gL);          // transition constant
        const float tS  = fmaf(gGS, Gn, gS);         // coeff of S_t
        const float tC  = fmaf(gGC, Gn, gC);         // coeff of C_t
        const float ob0 = fmaf(bG, Gn, b0) + bL;     // outcome constant
        const float oS  = fmaf(bGS, Gn, bS);         // outcome coeff of S_t

        const float4* __restrict__ S4 = reinterpret_cast<const float4*>(S) + (size_t)n * NCHUNK;
        const float4* __restrict__ C4 = reinterpret_cast<const float4*>(C) + (size_t)n * NCHUNK;
        const float4* __restrict__ Y4 = reinterpret_cast<const float4*>(Y) + (size_t)n * NCHUNK;
        float4* __restrict__ ZF4 = reinterpret_cast<float4*>(Zf) + (size_t)n * NCHUNK;
        float4* __restrict__ ZV4 = reinterpret_cast<float4*>(Zv) + (size_t)n * NCHUNK;

        float Zm = 0.0f;     // filtered mean
        float Zr = 1.0f;     // filtered variance

#define STEP(s_, c_, y_, zf_, zv_)                                              \
        {                                                                       \
            float Zpred = fmaf(psi, Zm, fmaf(tS, (s_), fmaf(tC, (c_), tc0)));   \
            float Zpv   = fmaf(psi2, Zr, sigma2);                               \
            float logit = fmaf(bZ, Zpred, fmaf(oS, (s_), ob0));                 \
            logit = fminf(fmaxf(logit, -20.0f), 20.0f);                         \
            float e  = __expf(-logit);                                          \
            float p  = __fdividef(1.0f, 1.0f + e);                              \
            float pq = e * p * p;              /* p*(1-p) */                    \
            float hess = fmaf(bZ2, pq, 1e-6f);                                  \
            float Zpo  = __fdividef(Zpv, fmaf(Zpv, hess, 1.0f));                \
            float grad = ((y_) - p) * bZ;                                       \
            Zm = fmaf(Zpo, grad, Zpred);                                        \
            Zr = Zpo;                                                           \
            ll += (y_) * __logf(p + 1e-10f)                                     \
                + (1.0f - (y_)) * __logf(1.0f - p + 1e-10f);                    \
            (zf_) = Zm;                                                         \
            (zv_) = Zr;                                                         \
        }

#pragma unroll
        for (int ch = 0; ch < NCHUNK; ch++) {
            const float4 s4 = S4[ch];
            const float4 c4 = C4[ch];
            const float4 y4 = Y4[ch];
            float4 zf4, zv4;
            STEP(s4.x, c4.x, y4.x, zf4.x, zv4.x);
            STEP(s4.y, c4.y, y4.y, zf4.y, zv4.y);
            STEP(s4.z, c4.z, y4.z, zf4.z, zv4.z);
            STEP(s4.w, c4.w, y4.w, zf4.w, zv4.w);
            ZF4[ch] = zf4;
            ZV4[ch] = zv4;
        }
#undef STEP
    }

    // ---- block reduction of ll, one double atomic per block ----
    #pragma unroll
    for (int off = 16; off > 0; off >>= 1)
        ll += __shfl_down_sync(0xffffffffu, ll, off);

    __shared__ float wsum[8];
    const int lane = threadIdx.x & 31;
    const int wid  = threadIdx.x >> 5;
    if (lane == 0) wsum[wid] = ll;
    __syncthreads();

    if (threadIdx.x < 8) {
        float v = wsum[threadIdx.x];
        #pragma unroll
        for (int off = 4; off > 0; off >>= 1)
            v += __shfl_down_sync(0xffu, v, off);
        if (threadIdx.x == 0)
            atomicAdd(&g_ll, (double)v);
    }
}

extern "C" void kernel_launch(void* const* d_in, const int* in_sizes, int n_in,
                              void* d_out, int out_size)
{
    const float* G   = (const float*)d_in[0];
    const float* S   = (const float*)d_in[1];
    const float* C   = (const float*)d_in[2];
    const float* Y   = (const float*)d_in[3];
    const float* L   = (const float*)d_in[4];
    const float* psi = (const float*)d_in[5];
    const float* gS  = (const float*)d_in[6];
    const float* gC  = (const float*)d_in[7];
    const float* gG  = (const float*)d_in[8];
    const float* gGS = (const float*)d_in[9];
    const float* gGC = (const float*)d_in[10];
    const float* gLw = (const float*)d_in[11];
    const float* lsz = (const float*)d_in[12];
    const float* b0  = (const float*)d_in[13];
    const float* bZ  = (const float*)d_in[14];
    const float* bS  = (const float*)d_in[15];
    const float* bG  = (const float*)d_in[16];
    const float* bGS = (const float*)d_in[17];
    const float* bLw = (const float*)d_in[18];

    const int N = in_sizes[0];              // G is (N,1)
    const size_t NT = (size_t)N * T_STEPS;

    float* out = (float*)d_out;
    float* Zf  = out;                        // (N,T)
    float* Zv  = out + NT;                   // (N,T)
    float* llp = out + 2 * NT;               // scalar

    zero_ll_kernel<<<1, 1>>>();

    const int threads = 256;
    const int blocks  = (N + threads - 1) / threads;
    hmm_filter_kernel<<<blocks, threads>>>(
        G, S, C, Y, L,
        psi, gS, gC, gG, gGS, gGC, gLw, lsz,
        b0, bZ, bS, bG, bGS, bLw,
        Zf, Zv, N);

    finalize_ll_kernel<<<1, 1>>>(llp);
}

// round 2
// speedup vs baseline: 1.1176x; 1.1176x over previous
#include <cuda_runtime.h>
#include <math.h>

#define T_STEPS   64
#define TCH       8              // timesteps per chunk
#define NCH       (T_STEPS/TCH)  // 8 chunks
#define ROWS_PB   256            // rows per block
#define SSTRIDE   (TCH + 1)      // 9 floats: conflict-free (gcd(9,32)=1)
#define MAXBLOCKS 2048

// Deterministic per-block log-likelihood partials (device global: no allocs).
__device__ double g_part[MAXBLOCKS];

__global__ void finalize_ll_kernel(float* __restrict__ out_ll, int nblocks)
{
    double s = 0.0;
    for (int i = threadIdx.x; i < nblocks; i += 256)
        s += g_part[i];
    // warp reduce
    #pragma unroll
    for (int off = 16; off > 0; off >>= 1)
        s += __shfl_down_sync(0xffffffffu, s, off);
    __shared__ double ws[8];
    int lane = threadIdx.x & 31, wid = threadIdx.x >> 5;
    if (lane == 0) ws[wid] = s;
    __syncthreads();
    if (threadIdx.x < 8) {
        double v = ws[threadIdx.x];
        #pragma unroll
        for (int off = 4; off > 0; off >>= 1)
            v += __shfl_down_sync(0xffu, v, off);
        if (threadIdx.x == 0) *out_ll = (float)v;
    }
}

__global__ __launch_bounds__(256)
void hmm_filter_kernel(
    const float* __restrict__ G,   // (N,1)
    const float* __restrict__ S,   // (N,T)
    const float* __restrict__ C,   // (N,T)
    const float* __restrict__ Y,   // (N,T)
    const float* __restrict__ L,   // (N,3)
    const float* __restrict__ p_psi,
    const float* __restrict__ p_gS,
    const float* __restrict__ p_gC,
    const float* __restrict__ p_gG,
    const float* __restrict__ p_gGS,
    const float* __restrict__ p_gGC,
    const float* __restrict__ p_gLw,   // (1,3)
    const float* __restrict__ p_lsz,
    const float* __restrict__ p_b0,
    const float* __restrict__ p_bZ,
    const float* __restrict__ p_bS,
    const float* __restrict__ p_bG,
    const float* __restrict__ p_bGS,
    const float* __restrict__ p_bLw,   // (1,3)
    float* __restrict__ Zf,            // (N,T)
    float* __restrict__ Zv,            // (N,T)
    int N)
{
    __shared__ float Sb[ROWS_PB * SSTRIDE];
    __shared__ float Cb[ROWS_PB * SSTRIDE];
    __shared__ float Yb[ROWS_PB * SSTRIDE];
    __shared__ float wsum[8];

    // ---- scalar params ----
    const float psi  = __ldg(p_psi);
    const float gS   = __ldg(p_gS);
    const float gC   = __ldg(p_gC);
    const float gG   = __ldg(p_gG);
    const float gGS  = __ldg(p_gGS);
    const float gGC  = __ldg(p_gGC);
    const float lsz  = __ldg(p_lsz);
    const float b0   = __ldg(p_b0);
    const float bZ   = __ldg(p_bZ);
    const float bS   = __ldg(p_bS);
    const float bG   = __ldg(p_bG);
    const float bGS  = __ldg(p_bGS);
    const float gw0  = __ldg(p_gLw + 0), gw1 = __ldg(p_gLw + 1), gw2 = __ldg(p_gLw + 2);
    const float bw0  = __ldg(p_bLw + 0), bw1 = __ldg(p_bLw + 1), bw2 = __ldg(p_bLw + 2);

    const float sz     = expf(lsz);
    const float sigma2 = sz * sz;
    const float psi2   = psi * psi;
    const float bZ2    = bZ * bZ;

    const int tid  = threadIdx.x;
    const int row0 = blockIdx.x * ROWS_PB;
    const int row  = row0 + tid;
    const bool valid = (row < N);

    // Per-row fused constants
    float tc0 = 0.f, tS = 0.f, tC = 0.f, ob0 = 0.f, oS = 0.f;
    if (valid) {
        const float Gn = __ldg(G + row);
        const float l0 = __ldg(L + 3 * (size_t)row + 0);
        const float l1 = __ldg(L + 3 * (size_t)row + 1);
        const float l2 = __ldg(L + 3 * (size_t)row + 2);
        const float gL = fmaf(gw0, l0, fmaf(gw1, l1, gw2 * l2));
        const float bL = fmaf(bw0, l0, fmaf(bw1, l1, bw2 * l2));
        tc0 = fmaf(gG, Gn, gL);
        tS  = fmaf(gGS, Gn, gS);
        tC  = fmaf(gGC, Gn, gC);
        ob0 = fmaf(bG, Gn, b0) + bL;
        oS  = fmaf(bGS, Gn, bS);
    }

    const float4* __restrict__ S4  = reinterpret_cast<const float4*>(S);
    const float4* __restrict__ C4  = reinterpret_cast<const float4*>(C);
    const float4* __restrict__ Y4  = reinterpret_cast<const float4*>(Y);
    float4* __restrict__ ZF4 = reinterpret_cast<float4*>(Zf);
    float4* __restrict__ ZV4 = reinterpret_cast<float4*>(Zv);

    float Zm = 0.0f;     // filtered mean
    float Zr = 1.0f;     // filtered variance
    float ll = 0.0f;

#define STEP(s_, c_, y_, zf_, zv_)                                              \
        {                                                                       \
            float Zpred = fmaf(psi, Zm, fmaf(tS, (s_), fmaf(tC, (c_), tc0)));   \
            float Zpv   = fmaf(psi2, Zr, sigma2);                               \
            float logit = fmaf(bZ, Zpred, fmaf(oS, (s_), ob0));                 \
            logit = fminf(fmaxf(logit, -20.0f), 20.0f);                         \
            float e  = __expf(-logit);                                          \
            float p  = __fdividef(1.0f, 1.0f + e);                              \
            float pq = e * p * p;              /* p*(1-p) */                    \
            float hess = fmaf(bZ2, pq, 1e-6f);                                  \
            float Zpo  = __fdividef(Zpv, fmaf(Zpv, hess, 1.0f));                \
            float grad = ((y_) - p) * bZ;                                       \
            Zm = fmaf(Zpo, grad, Zpred);                                        \
            Zr = Zpo;                                                           \
            ll += (y_) * __logf(p + 1e-10f)                                     \
                + (1.0f - (y_)) * __logf(1.0f - p + 1e-10f);                    \
            (zf_) = Zm;                                                         \
            (zv_) = Zr;                                                         \
        }

    #pragma unroll 1
    for (int ch = 0; ch < NCH; ch++) {
        __syncthreads();   // flush reads of previous chunk done before overwrite

        // ---- coalesced staged load: 2 float4 per thread per array ----
        #pragma unroll
        for (int k = 0; k < 2; k++) {
            const int f = tid + k * 256;
            const int r = f >> 1;
            const int j = f & 1;
            const int rr = row0 + r;
            if (rr < N) {
                const size_t g = (size_t)rr * (T_STEPS / 4) + ch * 2 + j;
                const float4 s = S4[g];
                const float4 c = C4[g];
                const float4 y = Y4[g];
                const int b = r * SSTRIDE + j * 4;
                Sb[b + 0] = s.x; Sb[b + 1] = s.y; Sb[b + 2] = s.z; Sb[b + 3] = s.w;
                Cb[b + 0] = c.x; Cb[b + 1] = c.y; Cb[b + 2] = c.z; Cb[b + 3] = c.w;
                Yb[b + 0] = y.x; Yb[b + 1] = y.y; Yb[b + 2] = y.z; Yb[b + 3] = y.w;
            }
        }
        __syncthreads();

        // ---- compute: conflict-free smem row access, overwrite Sb/Cb with Zf/Zv ----
        if (valid) {
            const int base = tid * SSTRIDE;
            #pragma unroll
            for (int t = 0; t < TCH; t++) {
                const float s_ = Sb[base + t];
                const float c_ = Cb[base + t];
                const float y_ = Yb[base + t];
                float zf_, zv_;
                STEP(s_, c_, y_, zf_, zv_);
                Sb[base + t] = zf_;
                Cb[base + t] = zv_;
            }
        }
        __syncthreads();

        // ---- coalesced staged flush ----
        #pragma unroll
        for (int k = 0; k < 2; k++) {
            const int f = tid + k * 256;
            const int r = f >> 1;
            const int j = f & 1;
            const int rr = row0 + r;
            if (rr < N) {
                const int b = r * SSTRIDE + j * 4;
                float4 zf4, zv4;
                zf4.x = Sb[b + 0]; zf4.y = Sb[b + 1]; zf4.z = Sb[b + 2]; zf4.w = Sb[b + 3];
                zv4.x = Cb[b + 0]; zv4.y = Cb[b + 1]; zv4.z = Cb[b + 2]; zv4.w = Cb[b + 3];
                const size_t g = (size_t)rr * (T_STEPS / 4) + ch * 2 + j;
                ZF4[g] = zf4;
                ZV4[g] = zv4;
            }
        }
    }
#undef STEP

    // ---- deterministic block reduction of ll ----
    #pragma unroll
    for (int off = 16; off > 0; off >>= 1)
        ll += __shfl_down_sync(0xffffffffu, ll, off);

    const int lane = tid & 31;
    const int wid  = tid >> 5;
    if (lane == 0) wsum[wid] = ll;
    __syncthreads();

    if (tid < 8) {
        float v = wsum[tid];
        #pragma unroll
        for (int off = 4; off > 0; off >>= 1)
            v += __shfl_down_sync(0xffu, v, off);
        if (tid == 0)
            g_part[blockIdx.x] = (double)v;
    }
}

extern "C" void kernel_launch(void* const* d_in, const int* in_sizes, int n_in,
                              void* d_out, int out_size)
{
    const float* G   = (const float*)d_in[0];
    const float* S   = (const float*)d_in[1];
    const float* C   = (const float*)d_in[2];
    const float* Y   = (const float*)d_in[3];
    const float* L   = (const float*)d_in[4];
    const float* psi = (const float*)d_in[5];
    const float* gS  = (const float*)d_in[6];
    const float* gC  = (const float*)d_in[7];
    const float* gG  = (const float*)d_in[8];
    const float* gGS = (const float*)d_in[9];
    const float* gGC = (const float*)d_in[10];
    const float* gLw = (const float*)d_in[11];
    const float* lsz = (const float*)d_in[12];
    const float* b0  = (const float*)d_in[13];
    const float* bZ  = (const float*)d_in[14];
    const float* bS  = (const float*)d_in[15];
    const float* bG  = (const float*)d_in[16];
    const float* bGS = (const float*)d_in[17];
    const float* bLw = (const float*)d_in[18];

    const int N = in_sizes[0];              // G is (N,1)
    const size_t NT = (size_t)N * T_STEPS;

    float* out = (float*)d_out;
    float* Zf  = out;                        // (N,T)
    float* Zv  = out + NT;                   // (N,T)
    float* llp = out + 2 * NT;               // scalar

    const int threads = 256;
    const int blocks  = (N + ROWS_PB - 1) / ROWS_PB;

    hmm_filter_kernel<<<blocks, threads>>>(
        G, S, C, Y, L,
        psi, gS, gC, gG, gGS, gGC, gLw, lsz,
        b0, bZ, bS, bG, bGS, bLw,
        Zf, Zv, N);

    finalize_ll_kernel<<<1, 256>>>(llp, blocks);
}

// round 3
// speedup vs baseline: 1.7435x; 1.5601x over previous
#include <cuda_runtime.h>
#include <math.h>

#define T_STEPS   64
#define TCH       16             // timesteps per chunk (64B per row per array)
#define NCH       (T_STEPS/TCH)  // 4 chunks
#define ROWS_PB   192            // rows per block == threads per block
#define SSTRIDE   (TCH + 1)      // 17: gcd(17,32)=1 -> conflict-free compute phase
#define MAXBLOCKS 4096

// Deterministic per-block log-likelihood partials + self-resetting ticket.
__device__ double       g_part[MAXBLOCKS];
__device__ unsigned int g_ticket;   // zero-init; last block resets to 0

__global__ __launch_bounds__(ROWS_PB)
void hmm_filter_kernel(
    const float* __restrict__ G,   // (N,1)
    const float* __restrict__ S,   // (N,T)
    const float* __restrict__ C,   // (N,T)
    const float* __restrict__ Y,   // (N,T)
    const float* __restrict__ L,   // (N,3)
    const float* __restrict__ p_psi,
    const float* __restrict__ p_gS,
    const float* __restrict__ p_gC,
    const float* __restrict__ p_gG,
    const float* __restrict__ p_gGS,
    const float* __restrict__ p_gGC,
    const float* __restrict__ p_gLw,   // (1,3)
    const float* __restrict__ p_lsz,
    const float* __restrict__ p_b0,
    const float* __restrict__ p_bZ,
    const float* __restrict__ p_bS,
    const float* __restrict__ p_bG,
    const float* __restrict__ p_bGS,
    const float* __restrict__ p_bLw,   // (1,3)
    float* __restrict__ Zf,            // (N,T)
    float* __restrict__ Zv,            // (N,T)
    float* __restrict__ out_ll,
    int N)
{
    __shared__ float Sb[ROWS_PB * SSTRIDE];
    __shared__ float Cb[ROWS_PB * SSTRIDE];
    __shared__ float Yb[ROWS_PB * SSTRIDE];
    __shared__ float  wsum[ROWS_PB / 32];
    __shared__ double dsum[ROWS_PB / 32];
    __shared__ bool   is_last;

    // ---- scalar params ----
    const float psi  = __ldg(p_psi);
    const float gS   = __ldg(p_gS);
    const float gC   = __ldg(p_gC);
    const float gG   = __ldg(p_gG);
    const float gGS  = __ldg(p_gGS);
    const float gGC  = __ldg(p_gGC);
    const float lsz  = __ldg(p_lsz);
    const float b0   = __ldg(p_b0);
    const float bZ   = __ldg(p_bZ);
    const float bS   = __ldg(p_bS);
    const float bG   = __ldg(p_bG);
    const float bGS  = __ldg(p_bGS);
    const float gw0  = __ldg(p_gLw + 0), gw1 = __ldg(p_gLw + 1), gw2 = __ldg(p_gLw + 2);
    const float bw0  = __ldg(p_bLw + 0), bw1 = __ldg(p_bLw + 1), bw2 = __ldg(p_bLw + 2);

    const float sz     = expf(lsz);
    const float sigma2 = sz * sz;
    const float psi2   = psi * psi;
    const float bZ2    = bZ * bZ;

    const int tid  = threadIdx.x;
    const int row0 = blockIdx.x * ROWS_PB;
    const int row  = row0 + tid;
    const bool valid = (row < N);

    // Per-row fused constants
    float tc0 = 0.f, tS = 0.f, tC = 0.f, ob0 = 0.f, oS = 0.f;
    if (valid) {
        const float Gn = __ldg(G + row);
        const float l0 = __ldg(L + 3 * (size_t)row + 0);
        const float l1 = __ldg(L + 3 * (size_t)row + 1);
        const float l2 = __ldg(L + 3 * (size_t)row + 2);
        const float gL = fmaf(gw0, l0, fmaf(gw1, l1, gw2 * l2));
        const float bL = fmaf(bw0, l0, fmaf(bw1, l1, bw2 * l2));
        tc0 = fmaf(gG, Gn, gL);
        tS  = fmaf(gGS, Gn, gS);
        tC  = fmaf(gGC, Gn, gC);
        ob0 = fmaf(bG, Gn, b0) + bL;
        oS  = fmaf(bGS, Gn, bS);
    }

    const float4* __restrict__ S4  = reinterpret_cast<const float4*>(S);
    const float4* __restrict__ C4  = reinterpret_cast<const float4*>(C);
    const float4* __restrict__ Y4  = reinterpret_cast<const float4*>(Y);
    float4* __restrict__ ZF4 = reinterpret_cast<float4*>(Zf);
    float4* __restrict__ ZV4 = reinterpret_cast<float4*>(Zv);

    float Zm = 0.0f;     // filtered mean
    float Zr = 1.0f;     // filtered variance
    float ll = 0.0f;

#define STEP(s_, c_, y_, zf_, zv_)                                              \
        {                                                                       \
            float Zpred = fmaf(psi, Zm, fmaf(tS, (s_), fmaf(tC, (c_), tc0)));   \
            float Zpv   = fmaf(psi2, Zr, sigma2);                               \
            float logit = fmaf(bZ, Zpred, fmaf(oS, (s_), ob0));                 \
            logit = fminf(fmaxf(logit, -20.0f), 20.0f);                         \
            float e  = __expf(-logit);                                          \
            float p  = __fdividef(1.0f, 1.0f + e);                              \
            float pq = e * p * p;              /* p*(1-p) */                    \
            float hess = fmaf(bZ2, pq, 1e-6f);                                  \
            float Zpo  = __fdividef(Zpv, fmaf(Zpv, hess, 1.0f));                \
            float grad = ((y_) - p) * bZ;                                       \
            Zm = fmaf(Zpo, grad, Zpred);                                        \
            Zr = Zpo;                                                           \
            /* y in {0,1}: y*log(p+eps)+(1-y)*log(1-p+eps) == log(sel+eps) */   \
            float sel = ((y_) != 0.0f) ? p : (1.0f - p);                        \
            ll += __logf(sel + 1e-10f);                                         \
            (zf_) = Zm;                                                         \
            (zv_) = Zr;                                                         \
        }

    #pragma unroll 1
    for (int ch = 0; ch < NCH; ch++) {
        __syncthreads();   // previous chunk's flush reads done before overwrite

        // ---- coalesced staged load: warp reads 8 rows x 64B contiguous ----
        #pragma unroll
        for (int k = 0; k < 4; k++) {
            const int f = tid + k * ROWS_PB;   // 0..4*ROWS_PB-1
            const int r = f >> 2;              // row within block
            const int j = f & 3;               // float4 within 64B granule
            const int rr = row0 + r;
            if (rr < N) {
                const size_t g = (size_t)rr * (T_STEPS / 4) + ch * 4 + j;
                const float4 s = S4[g];
                const float4 c = C4[g];
                const float4 y = Y4[g];
                const int b = r * SSTRIDE + j * 4;
                Sb[b + 0] = s.x; Sb[b + 1] = s.y; Sb[b + 2] = s.z; Sb[b + 3] = s.w;
                Cb[b + 0] = c.x; Cb[b + 1] = c.y; Cb[b + 2] = c.z; Cb[b + 3] = c.w;
                Yb[b + 0] = y.x; Yb[b + 1] = y.y; Yb[b + 2] = y.z; Yb[b + 3] = y.w;
            }
        }
        __syncthreads();

        // ---- compute: conflict-free smem rows, overwrite Sb/Cb with Zf/Zv ----
        if (valid) {
            const int base = tid * SSTRIDE;
            #pragma unroll
            for (int t = 0; t < TCH; t++) {
                const float s_ = Sb[base + t];
                const float c_ = Cb[base + t];
                const float y_ = Yb[base + t];
                float zf_, zv_;
                STEP(s_, c_, y_, zf_, zv_);
                Sb[base + t] = zf_;
                Cb[base + t] = zv_;
            }
        }
        __syncthreads();

        // ---- coalesced staged flush: warp writes 8 rows x 64B contiguous ----
        #pragma unroll
        for (int k = 0; k < 4; k++) {
            const int f = tid + k * ROWS_PB;
            const int r = f >> 2;
            const int j = f & 3;
            const int rr = row0 + r;
            if (rr < N) {
                const int b = r * SSTRIDE + j * 4;
                float4 zf4, zv4;
                zf4.x = Sb[b + 0]; zf4.y = Sb[b + 1]; zf4.z = Sb[b + 2]; zf4.w = Sb[b + 3];
                zv4.x = Cb[b + 0]; zv4.y = Cb[b + 1]; zv4.z = Cb[b + 2]; zv4.w = Cb[b + 3];
                const size_t g = (size_t)rr * (T_STEPS / 4) + ch * 4 + j;
                ZF4[g] = zf4;
                ZV4[g] = zv4;
            }
        }
    }
#undef STEP

    // ---- deterministic block reduction of ll ----
    #pragma unroll
    for (int off = 16; off > 0; off >>= 1)
        ll += __shfl_down_sync(0xffffffffu, ll, off);

    const int lane = tid & 31;
    const int wid  = tid >> 5;
    if (lane == 0) wsum[wid] = ll;
    __syncthreads();

    if (tid == 0) {
        float v = 0.0f;
        #pragma unroll
        for (int w = 0; w < ROWS_PB / 32; w++) v += wsum[w];
        g_part[blockIdx.x] = (double)v;
        __threadfence();
        unsigned int ticket = atomicAdd(&g_ticket, 1u);
        is_last = (ticket == gridDim.x - 1);
        if (is_last) g_ticket = 0;    // self-reset for next (replay) launch
    }
    __syncthreads();

    // ---- last block: deterministic final reduction ----
    if (is_last) {
        double s = 0.0;
        for (int i = tid; i < (int)gridDim.x; i += ROWS_PB)
            s += g_part[i];
        #pragma unroll
        for (int off = 16; off > 0; off >>= 1)
            s += __shfl_down_sync(0xffffffffu, s, off);
        if (lane == 0) dsum[wid] = s;
        __syncthreads();
        if (tid == 0) {
            double v = 0.0;
            #pragma unroll
            for (int w = 0; w < ROWS_PB / 32; w++) v += dsum[w];
            *out_ll = (float)v;
        }
    }
}

extern "C" void kernel_launch(void* const* d_in, const int* in_sizes, int n_in,
                              void* d_out, int out_size)
{
    const float* G   = (const float*)d_in[0];
    const float* S   = (const float*)d_in[1];
    const float* C   = (const float*)d_in[2];
    const float* Y   = (const float*)d_in[3];
    const float* L   = (const float*)d_in[4];
    const float* psi = (const float*)d_in[5];
    const float* gS  = (const float*)d_in[6];
    const float* gC  = (const float*)d_in[7];
    const float* gG  = (const float*)d_in[8];
    const float* gGS = (const float*)d_in[9];
    const float* gGC = (const float*)d_in[10];
    const float* gLw = (const float*)d_in[11];
    const float* lsz = (const float*)d_in[12];
    const float* b0  = (const float*)d_in[13];
    const float* bZ  = (const float*)d_in[14];
    const float* bS  = (const float*)d_in[15];
    const float* bG  = (const float*)d_in[16];
    const float* bGS = (const float*)d_in[17];
    const float* bLw = (const float*)d_in[18];

    const int N = in_sizes[0];              // G is (N,1)
    const size_t NT = (size_t)N * T_STEPS;

    float* out = (float*)d_out;
    float* Zf  = out;                        // (N,T)
    float* Zv  = out + NT;                   // (N,T)
    float* llp = out + 2 * NT;               // scalar

    const int blocks = (N + ROWS_PB - 1) / ROWS_PB;

    hmm_filter_kernel<<<blocks, ROWS_PB>>>(
        G, S, C, Y, L,
        psi, gS, gC, gG, gGS, gGC, gLw, lsz,
        b0, bZ, bS, bG, bGS, bLw,
        Zf, Zv, llp, N);
}

// round 4
// speedup vs baseline: 1.9384x; 1.1118x over previous
#include <cuda_runtime.h>
#include <math.h>

#define T_STEPS   64
#define TCH       16             // timesteps per chunk (64B per row per array)
#define NCH       (T_STEPS/TCH)  // 4 chunks
#define WARPS_PB  6
#define ROWS_PB   (WARPS_PB*32)  // 192 rows per block == threads per block
#define SSTRIDE   (TCH + 1)      // 17: conflict-free compute phase (gcd(17,32)=1)
#define SLAB      (32 * SSTRIDE) // floats per warp slab
#define MAXBLOCKS 4096

// Deterministic per-block log-likelihood partials + self-resetting ticket.
__device__ double       g_part[MAXBLOCKS];
__device__ unsigned int g_ticket;   // zero-init; last block resets to 0

__global__ __launch_bounds__(ROWS_PB, 4)
void hmm_filter_kernel(
    const float* __restrict__ G,   // (N,1)
    const float* __restrict__ S,   // (N,T)
    const float* __restrict__ C,   // (N,T)
    const float* __restrict__ Y,   // (N,T)
    const float* __restrict__ L,   // (N,3)
    const float* __restrict__ p_psi,
    const float* __restrict__ p_gS,
    const float* __restrict__ p_gC,
    const float* __restrict__ p_gG,
    const float* __restrict__ p_gGS,
    const float* __restrict__ p_gGC,
    const float* __restrict__ p_gLw,   // (1,3)
    const float* __restrict__ p_lsz,
    const float* __restrict__ p_b0,
    const float* __restrict__ p_bZ,
    const float* __restrict__ p_bS,
    const float* __restrict__ p_bG,
    const float* __restrict__ p_bGS,
    const float* __restrict__ p_bLw,   // (1,3)
    float* __restrict__ Zf,            // (N,T)
    float* __restrict__ Zv,            // (N,T)
    float* __restrict__ out_ll,
    int N)
{
    // Warp-private slabs: no cross-warp sharing -> __syncwarp only.
    __shared__ float Sb[WARPS_PB][SLAB];
    __shared__ float Cb[WARPS_PB][SLAB];
    __shared__ float Yb[WARPS_PB][SLAB];
    __shared__ float  wsum[WARPS_PB];
    __shared__ double dsum[WARPS_PB];
    __shared__ bool   is_last;

    // ---- scalar params ----
    const float psi  = __ldg(p_psi);
    const float gS   = __ldg(p_gS);
    const float gC   = __ldg(p_gC);
    const float gG   = __ldg(p_gG);
    const float gGS  = __ldg(p_gGS);
    const float gGC  = __ldg(p_gGC);
    const float lsz  = __ldg(p_lsz);
    const float b0   = __ldg(p_b0);
    const float bZ   = __ldg(p_bZ);
    const float bS   = __ldg(p_bS);
    const float bG   = __ldg(p_bG);
    const float bGS  = __ldg(p_bGS);
    const float gw0  = __ldg(p_gLw + 0), gw1 = __ldg(p_gLw + 1), gw2 = __ldg(p_gLw + 2);
    const float bw0  = __ldg(p_bLw + 0), bw1 = __ldg(p_bLw + 1), bw2 = __ldg(p_bLw + 2);

    const float sz     = expf(lsz);
    const float sigma2 = sz * sz;
    const float psi2   = psi * psi;
    const float bZ2    = bZ * bZ;

    const int tid  = threadIdx.x;
    const int lane = tid & 31;
    const int wid  = tid >> 5;
    const int row0w = blockIdx.x * ROWS_PB + wid * 32;  // warp's first row
    const int row   = row0w + lane;
    const bool valid = (row < N);

    float* const sS = Sb[wid];
    float* const sC = Cb[wid];
    float* const sY = Yb[wid];

    // Per-row fused constants
    float tc0 = 0.f, tS = 0.f, tC = 0.f, ob0 = 0.f, oS = 0.f;
    if (valid) {
        const float Gn = __ldg(G + row);
        const float l0 = __ldg(L + 3 * (size_t)row + 0);
        const float l1 = __ldg(L + 3 * (size_t)row + 1);
        const float l2 = __ldg(L + 3 * (size_t)row + 2);
        const float gL = fmaf(gw0, l0, fmaf(gw1, l1, gw2 * l2));
        const float bL = fmaf(bw0, l0, fmaf(bw1, l1, bw2 * l2));
        tc0 = fmaf(gG, Gn, gL);
        tS  = fmaf(gGS, Gn, gS);
        tC  = fmaf(gGC, Gn, gC);
        ob0 = fmaf(bG, Gn, b0) + bL;
        oS  = fmaf(bGS, Gn, bS);
    }

    const float4* __restrict__ S4  = reinterpret_cast<const float4*>(S);
    const float4* __restrict__ C4  = reinterpret_cast<const float4*>(C);
    const float4* __restrict__ Y4  = reinterpret_cast<const float4*>(Y);
    float4* __restrict__ ZF4 = reinterpret_cast<float4*>(Zf);
    float4* __restrict__ ZV4 = reinterpret_cast<float4*>(Zv);

    float Zm = 0.0f;     // filtered mean
    float Zr = 1.0f;     // filtered variance
    float ll = 0.0f;

#define STEP(s_, c_, y_, zf_, zv_)                                              \
        {                                                                       \
            float Zpred = fmaf(psi, Zm, fmaf(tS, (s_), fmaf(tC, (c_), tc0)));   \
            float Zpv   = fmaf(psi2, Zr, sigma2);                               \
            float logit = fmaf(bZ, Zpred, fmaf(oS, (s_), ob0));                 \
            logit = fminf(fmaxf(logit, -20.0f), 20.0f);                         \
            float e  = __expf(-logit);                                          \
            float p  = __fdividef(1.0f, 1.0f + e);                              \
            float pq = e * p * p;              /* p*(1-p) */                    \
            float hess = fmaf(bZ2, pq, 1e-6f);                                  \
            float Zpo  = __fdividef(Zpv, fmaf(Zpv, hess, 1.0f));                \
            float grad = ((y_) - p) * bZ;                                       \
            Zm = fmaf(Zpo, grad, Zpred);                                        \
            Zr = Zpo;                                                           \
            /* y in {0,1}: y*log(p+eps)+(1-y)*log(1-p+eps) == log(sel+eps) */   \
            float sel = ((y_) != 0.0f) ? p : (1.0f - p);                        \
            ll += __logf(sel + 1e-10f);                                         \
            (zf_) = Zm;                                                         \
            (zv_) = Zr;                                                         \
        }

    #pragma unroll 1
    for (int ch = 0; ch < NCH; ch++) {
        // ---- coalesced warp load: 8 rows x 64B contiguous per step ----
        #pragma unroll
        for (int k = 0; k < 4; k++) {
            const int f = lane + k * 32;   // 0..127
            const int r = f >> 2;          // row within warp
            const int j = f & 3;           // float4 within 64B granule
            const int rr = row0w + r;
            if (rr < N) {
                const size_t g = (size_t)rr * (T_STEPS / 4) + ch * 4 + j;
                const float4 s = S4[g];
                const float4 c = C4[g];
                const float4 y = Y4[g];
                const int b = r * SSTRIDE + j * 4;
                sS[b + 0] = s.x; sS[b + 1] = s.y; sS[b + 2] = s.z; sS[b + 3] = s.w;
                sC[b + 0] = c.x; sC[b + 1] = c.y; sC[b + 2] = c.z; sC[b + 3] = c.w;
                sY[b + 0] = y.x; sY[b + 1] = y.y; sY[b + 2] = y.z; sY[b + 3] = y.w;
            }
        }
        __syncwarp();

        // ---- compute: conflict-free smem rows, overwrite sS/sC with Zf/Zv ----
        if (valid) {
            const int base = lane * SSTRIDE;
            #pragma unroll
            for (int t = 0; t < TCH; t++) {
                const float s_ = sS[base + t];
                const float c_ = sC[base + t];
                const float y_ = sY[base + t];
                float zf_, zv_;
                STEP(s_, c_, y_, zf_, zv_);
                sS[base + t] = zf_;
                sC[base + t] = zv_;
            }
        }
        __syncwarp();

        // ---- coalesced warp flush ----
        #pragma unroll
        for (int k = 0; k < 4; k++) {
            const int f = lane + k * 32;
            const int r = f >> 2;
            const int j = f & 3;
            const int rr = row0w + r;
            if (rr < N) {
                const int b = r * SSTRIDE + j * 4;
                float4 zf4, zv4;
                zf4.x = sS[b + 0]; zf4.y = sS[b + 1]; zf4.z = sS[b + 2]; zf4.w = sS[b + 3];
                zv4.x = sC[b + 0]; zv4.y = sC[b + 1]; zv4.z = sC[b + 2]; zv4.w = sC[b + 3];
                const size_t g = (size_t)rr * (T_STEPS / 4) + ch * 4 + j;
                ZF4[g] = zf4;
                ZV4[g] = zv4;
            }
        }
        __syncwarp();   // flush reads done before next chunk overwrites slab
    }
#undef STEP

    // ---- deterministic block reduction of ll ----
    #pragma unroll
    for (int off = 16; off > 0; off >>= 1)
        ll += __shfl_down_sync(0xffffffffu, ll, off);

    if (lane == 0) wsum[wid] = ll;
    __syncthreads();

    if (tid == 0) {
        float v = 0.0f;
        #pragma unroll
        for (int w = 0; w < WARPS_PB; w++) v += wsum[w];
        g_part[blockIdx.x] = (double)v;
        __threadfence();
        unsigned int ticket = atomicAdd(&g_ticket, 1u);
        is_last = (ticket == gridDim.x - 1);
        if (is_last) g_ticket = 0;    // self-reset for replay launches
    }
    __syncthreads();

    // ---- last block: deterministic final reduction ----
    if (is_last) {
        double s = 0.0;
        for (int i = tid; i < (int)gridDim.x; i += ROWS_PB)
            s += g_part[i];
        #pragma unroll
        for (int off = 16; off > 0; off >>= 1)
            s += __shfl_down_sync(0xffffffffu, s, off);
        if (lane == 0) dsum[wid] = s;
        __syncthreads();
        if (tid == 0) {
            double v = 0.0;
            #pragma unroll
            for (int w = 0; w < WARPS_PB; w++) v += dsum[w];
            *out_ll = (float)v;
        }
    }
}

extern "C" void kernel_launch(void* const* d_in, const int* in_sizes, int n_in,
                              void* d_out, int out_size)
{
    const float* G   = (const float*)d_in[0];
    const float* S   = (const float*)d_in[1];
    const float* C   = (const float*)d_in[2];
    const float* Y   = (const float*)d_in[3];
    const float* L   = (const float*)d_in[4];
    const float* psi = (const float*)d_in[5];
    const float* gS  = (const float*)d_in[6];
    const float* gC  = (const float*)d_in[7];
    const float* gG  = (const float*)d_in[8];
    const float* gGS = (const float*)d_in[9];
    const float* gGC = (const float*)d_in[10];
    const float* gLw = (const float*)d_in[11];
    const float* lsz = (const float*)d_in[12];
    const float* b0  = (const float*)d_in[13];
    const float* bZ  = (const float*)d_in[14];
    const float* bS  = (const float*)d_in[15];
    const float* bG  = (const float*)d_in[16];
    const float* bGS = (const float*)d_in[17];
    const float* bLw = (const float*)d_in[18];

    const int N = in_sizes[0];              // G is (N,1)
    const size_t NT = (size_t)N * T_STEPS;

    float* out = (float*)d_out;
    float* Zf  = out;                        // (N,T)
    float* Zv  = out + NT;                   // (N,T)
    float* llp = out + 2 * NT;               // scalar

    const int blocks = (N + ROWS_PB - 1) / ROWS_PB;

    hmm_filter_kernel<<<blocks, ROWS_PB>>>(
        G, S, C, Y, L,
        psi, gS, gC, gG, gGS, gGC, gLw, lsz,
        b0, bZ, bS, bG, bGS, bLw,
        Zf, Zv, llp, N);
}